// round 8
// baseline (speedup 1.0000x reference)
#include <cuda_runtime.h>
#include <cuda_bf16.h>
#include <math.h>

// ---------------------------------------------------------------------------
// Problem constants
// ---------------------------------------------------------------------------
#define BATCH 32
#define NTOK  16384
#define DIM   64
#define NC    36          // FG_NUM + BG_NUM
#define NCP   40          // padded cluster count (4 zero dummies)
#define FG    32
#define ALPHA 10.0f
#define EPS   1e-12f
#define LOG2E 1.4426950408889634f

#define SPLIT 64          // CTAs per batch -> 2048 CTAs (makespan 5/4.61 = 92% eff @occ3)
#define TILE  128         // tokens per tile
#define TILES_PER_CTA (NTOK / SPLIT / TILE)   // 2
#define NT    128         // 4 warps

// Strides (floats)
#define XS_STRIDE  68     // 17 x 16B (odd) -> conflict-free row 16B-vec AND column scalar
#define CNT_STRIDE 64     // broadcast reads only
#define AP_STRIDE  44     // 11 x 16B (odd) -> conflict-free STS.128 rows, 40 payload

// Shared memory carve (floats)
#define SM_XS  0
#define SM_CNT (SM_XS  + TILE * XS_STRIDE)     // 8704
#define SM_AP  (SM_CNT + NC * CNT_STRIDE)      // 11008
#define SM_TOT (SM_AP  + TILE * AP_STRIDE)     // 16640 floats = 66560 B -> occ 3

// Device-global scratch (static; no allocation)
__device__ float g_cn[NC * DIM];                   // normalized centroids, c-major [c][d]
__device__ float g_ws[BATCH * SPLIT * DIM * NC];   // per-CTA partial weighted sums (18.9 MB)

// ---------------------------------------------------------------------------
// f32x2 packed helpers (PTX ISA 8.6, sm_100+)
// ---------------------------------------------------------------------------
typedef unsigned long long u64;

__device__ __forceinline__ u64 pk(float a, float b) {
    u64 r; asm("mov.b64 %0, {%1, %2};" : "=l"(r) : "f"(a), "f"(b)); return r;
}
__device__ __forceinline__ void upk(u64 v, float& a, float& b) {
    asm("mov.b64 {%0, %1}, %2;" : "=f"(a), "=f"(b) : "l"(v));
}
__device__ __forceinline__ u64 fma2(u64 a, u64 b, u64 c) {
    u64 d; asm("fma.rn.f32x2 %0, %1, %2, %3;" : "=l"(d) : "l"(a), "l"(b), "l"(c)); return d;
}
__device__ __forceinline__ float ex2f(float x) {
    float r; asm("ex2.approx.f32 %0, %1;" : "=f"(r) : "f"(x)); return r;
}

// ---------------------------------------------------------------------------
// Kernel 0: normalize centroids once into g_cn (c-major rows)
// ---------------------------------------------------------------------------
__global__ void vlad_prep(const float* __restrict__ cent) {
    int c = threadIdx.x;
    if (c < NC) {
        float ss = 0.f;
        #pragma unroll
        for (int d = 0; d < DIM; ++d) { float v = cent[d * NC + c]; ss += v * v; }
        float r = 1.0f / fmaxf(sqrtf(ss), EPS);
        #pragma unroll
        for (int d = 0; d < DIM; ++d) g_cn[c * DIM + d] = cent[d * NC + c] * r;
    }
}

// ---------------------------------------------------------------------------
// Main kernel: grid (SPLIT, BATCH), 128 threads, 66560 B dyn smem, occ 3
// Phase 1: thread owns token t=tid; cos row + fused softmax in registers.
//          All smem math operands loaded as ulonglong2 -> LDS.128 feeds FFMA2
//          register pairs directly, no packing MOVs.
// Phase 2: thread owns (d = tid&63, cluster-half of 20 = tid>>6), f32x2 over c.
// ---------------------------------------------------------------------------
__global__ void __launch_bounds__(NT, 3)
vlad_main(const float* __restrict__ x) {
    extern __shared__ float sm[];
    float* xs  = sm + SM_XS;    // [128][68] token-major raw x
    float* cnT = sm + SM_CNT;   // [36][64]  normalized centroids, c-major rows
    float* ap  = sm + SM_AP;    // [128][44] rinv * assign (40 payload, 4 zeros)

    const int tid = threadIdx.x;
    const int b   = blockIdx.y;
    const int bx  = blockIdx.x;

    // ---- copy normalized centroids to smem (coalesced, 18 floats/thread) ----
    #pragma unroll
    for (int i = tid; i < NC * DIM; i += NT) cnT[i] = g_cn[i];

    const int dd = tid & 63;     // dim owned in phase 2
    const int ch = tid >> 6;     // cluster half: 0 -> c 0..19, 1 -> c 20..39

    u64 acc[10];                 // persistent ws accumulators: 10 c-pairs
    #pragma unroll
    for (int j = 0; j < 10; ++j) acc[j] = pk(0.f, 0.f);

    const float* xb = x + ((size_t)b * NTOK + (size_t)bx * (NTOK / SPLIT)) * DIM;

    for (int tile = 0; tile < TILES_PER_CTA; ++tile) {
        const float4* xt = (const float4*)(xb + (size_t)tile * TILE * DIM);

        __syncthreads();   // protect xs/ap consumers of previous tile (and cnT copy)

        // ---- load tile: 2048 float4, coalesced LDG.128 -> conflict-free STS.128 ----
        #pragma unroll
        for (int j = 0; j < 16; ++j) {
            int i = tid + NT * j;
            float4 v = xt[i];
            int t = i >> 4, k = (i & 15) << 2;
            *(float4*)(xs + t * XS_STRIDE + k) = v;
        }
        __syncthreads();

        // ---- phase 1 + fused softmax: thread owns token t = tid ----
        {
            const int t = tid;
            // x row as 32 packed pairs, straight from LDS.128 (no pack movs)
            u64 xp[32];
            const ulonglong2* xr = (const ulonglong2*)(xs + t * XS_STRIDE);
            #pragma unroll
            for (int j = 0; j < 16; ++j) {
                ulonglong2 v = xr[j];
                xp[2*j] = v.x; xp[2*j+1] = v.y;
            }
            // inverse L2 norm
            u64 n0 = pk(0.f,0.f), n1 = pk(0.f,0.f);
            #pragma unroll
            for (int j = 0; j < 32; j += 2) {
                n0 = fma2(xp[j],   xp[j],   n0);
                n1 = fma2(xp[j+1], xp[j+1], n1);
            }
            float a0,a1,a2,a3; upk(n0,a0,a1); upk(n1,a2,a3);
            const float rinv = 1.0f / fmaxf(sqrtf((a0+a1)+(a2+a3)), EPS);

            // cos row: cn rows are warp-broadcast LDS.128 -> direct u64 pairs
            float cv[NCP];
            #pragma unroll
            for (int c = 0; c < NC; ++c) {
                const ulonglong2* cr = (const ulonglong2*)(cnT + c * CNT_STRIDE);
                u64 s0 = pk(0.f,0.f), s1 = pk(0.f,0.f);
                #pragma unroll
                for (int j = 0; j < 16; ++j) {
                    ulonglong2 w = cr[j];
                    s0 = fma2(xp[2*j],   w.x, s0);
                    s1 = fma2(xp[2*j+1], w.y, s1);
                }
                upk(s0,a0,a1); upk(s1,a2,a3);
                cv[c] = ((a0+a1)+(a2+a3)) * rinv;
            }
            // softmax over 36 real clusters
            float m = cv[0];
            #pragma unroll
            for (int c = 1; c < NC; ++c) m = fmaxf(m, cv[c]);
            float s = 0.f;
            #pragma unroll
            for (int c = 0; c < NC; ++c) {
                float e = ex2f((ALPHA * LOG2E) * (cv[c] - m));
                s += e; cv[c] = e;
            }
            cv[36] = 0.f; cv[37] = 0.f; cv[38] = 0.f; cv[39] = 0.f;
            const float ris = rinv / s;
            float* aprow = ap + t * AP_STRIDE;
            #pragma unroll
            for (int c = 0; c < NCP; c += 4)   // 10 conflict-free STS.128
                *(float4*)(aprow + c) = make_float4(cv[c]*ris, cv[c+1]*ris,
                                                    cv[c+2]*ris, cv[c+3]*ris);
        }
        __syncthreads();

        // ---- phase 2: ws[dd][c-pair] += x[t][dd] * a[t][c-pair] ----
        // 1 scalar LDS + 5 broadcast LDS.128 (u64 pairs direct) + 10 FFMA2 / token
        {
            const float* xcol  = xs + dd;           // conflict-free column scalars
            const float* abase = ap + ch * 20;      // 16B-aligned broadcast rows
            #pragma unroll 4
            for (int t = 0; t < TILE; ++t) {
                float xv = xcol[t * XS_STRIDE];
                u64 x2 = pk(xv, xv);                // the only pack in the hot path
                const ulonglong2* ar = (const ulonglong2*)(abase + t * AP_STRIDE);
                #pragma unroll
                for (int j = 0; j < 5; ++j) {
                    ulonglong2 av = ar[j];
                    acc[2*j]   = fma2(x2, av.x, acc[2*j]);
                    acc[2*j+1] = fma2(x2, av.y, acc[2*j+1]);
                }
            }
        }
    }

    // ---- write per-CTA partials (deterministic); ch1 drops the 2 dummy pairs ----
    float* wsp = g_ws + (size_t)(b * SPLIT + bx) * (DIM * NC) + dd * NC + ch * 20;
    const int npair = (ch == 0) ? 10 : 8;   // ch1 covers c20..35
    for (int j = 0; j < npair; ++j) {
        float lo, hi; upk(acc[j], lo, hi);
        ((float2*)wsp)[j] = make_float2(lo, hi);
    }
}

// ---------------------------------------------------------------------------
// Finalize: coalesced slot reduction into smem, then projection + L2 norms.
// sp[c] = sum_d cn[d][c]*ws[d][c] (exact identity). grid: BATCH, 256 threads.
// ---------------------------------------------------------------------------
__global__ void vlad_finalize(float* __restrict__ out) {
    __shared__ float wss[DIM * NC];    // reduced ws, [d][c]
    __shared__ float vl[NC * DIM];
    __shared__ float wsum[8];
    const int tid  = threadIdx.x;
    const int lane = tid & 31;
    const int w    = tid >> 5;    // 8 warps
    const int b    = blockIdx.x;

    // ---- stage 1: coalesced float4 reduction over SPLIT slots ----
    const float4* base = (const float4*)(g_ws + (size_t)b * SPLIT * (DIM * NC));
    #pragma unroll
    for (int i4 = tid; i4 < DIM * NC / 4; i4 += 256) {
        float4 acc = make_float4(0.f, 0.f, 0.f, 0.f);
        #pragma unroll 4
        for (int s = 0; s < SPLIT; ++s) {
            float4 v = base[(size_t)s * (DIM * NC / 4) + i4];
            acc.x += v.x; acc.y += v.y; acc.z += v.z; acc.w += v.w;
        }
        ((float4*)wss)[i4] = acc;
    }
    __syncthreads();

    // ---- stage 2: per-cluster projection + row L2 (all from smem / g_cn) ----
    float local = 0.f;
    for (int c = w; c < NC; c += 8) {
        const int d0 = lane, d1 = lane + 32;
        float v0 = wss[d0 * NC + c];
        float v1 = wss[d1 * NC + c];
        const float c0 = g_cn[c * DIM + d0], c1 = g_cn[c * DIM + d1];  // coalesced

        float sp = c0 * v0 + c1 * v1;
        #pragma unroll
        for (int o = 16; o > 0; o >>= 1) sp += __shfl_xor_sync(0xffffffffu, sp, o);

        v0 -= c0 * sp;
        v1 -= c1 * sp;

        float ss = v0 * v0 + v1 * v1;
        #pragma unroll
        for (int o = 16; o > 0; o >>= 1) ss += __shfl_xor_sync(0xffffffffu, ss, o);

        float r = 1.0f / fmaxf(sqrtf(ss), EPS);
        vl[c * DIM + d0] = v0 * r;
        vl[c * DIM + d1] = v1 * r;
        if (lane == 0) local += ss * r * r;   // per-row sumsq after row normalize
    }
    if (lane == 0) wsum[w] = local;
    __syncthreads();

    // deterministic fixed-order global reduction
    float tot = 0.f;
    #pragma unroll
    for (int j = 0; j < 8; ++j) tot += wsum[j];
    const float rt = 1.0f / fmaxf(sqrtf(tot), EPS);

    for (int i = tid; i < FG * DIM; i += 256)
        out[b * (FG * DIM) + i] = vl[i] * rt;
}

// ---------------------------------------------------------------------------
extern "C" void kernel_launch(void* const* d_in, const int* in_sizes, int n_in,
                              void* d_out, int out_size) {
    const float* x         = (const float*)d_in[0];   // (32, 16384, 64) fp32
    const float* centroids = (const float*)d_in[1];   // (64, 36) fp32
    float* out             = (float*)d_out;           // (32, 2048) fp32

    (void)in_sizes; (void)n_in; (void)out_size;

    cudaFuncSetAttribute(vlad_main, cudaFuncAttributeMaxDynamicSharedMemorySize,
                         SM_TOT * (int)sizeof(float));

    vlad_prep<<<1, 64>>>(centroids);
    vlad_main<<<dim3(SPLIT, BATCH), NT, SM_TOT * sizeof(float)>>>(x);
    vlad_finalize<<<BATCH, 256>>>(out);
}